// round 8
// baseline (speedup 1.0000x reference)
#include <cuda_runtime.h>
#include <math.h>

#define NHEAD  8
#define DMODEL 1024
#define DT     256
#define BATCH  32
#define KSZ    13
#define PADC   6
#define LLEN   1024

// ---------------------------------------------------------------------------
// Scratch arena (static device memory; no allocations anywhere).
// Offsets in floats.
// ---------------------------------------------------------------------------
#define OFF_QB   0ull                       // 32*256*1024        =  8388608
#define OFF_KB   8388608ull
#define OFF_VB   16777216ull
#define OFF_QS   25165824ull                // 8*32*256*256       = 16777216
#define OFF_KS   41943040ull
#define OFF_VS   58720256ull
#define OFF_SC   75497472ull                // scores             = 16777216
#define OFF_CAT  92274688ull                // 32*256*2048        = 16777216
#define OFF_PR   109051904ull               // 32*256*1024        =  8388608
#define OFF_FC   117440512ull
#define WS_TOTAL 125829120ull               // 480 MB

__device__ float g_ws[WS_TOTAL];

// ---------------------------------------------------------------------------
// conv1d: y[b,o,l] = sum_{c,t} w[o,c,t] * x[b,c,l+t-6] + bias[o]
// x: (B, 256, 1024), w: (256, 256, 13). Tile: 64 (o) x 128 (l), chunk 8 chans.
// 256 threads; micro-tile 4(o) x 8(l).
// ---------------------------------------------------------------------------
__global__ __launch_bounds__(256) void conv1d_kernel(
    const float* __restrict__ x, const float* __restrict__ w,
    const float* __restrict__ bias, float* __restrict__ y)
{
    const int b  = blockIdx.z;
    const int o0 = blockIdx.y * 64;
    const int l0 = blockIdx.x * 128;

    __shared__ float Ws[64][8 * KSZ];            // 64 x 104
    __shared__ float Xs[8][128 + 2 * PADC];      // 8 x 140

    const int tid = threadIdx.x;
    const int tl  = tid & 15;    // l group
    const int to  = tid >> 4;    // o group (0..15)

    float acc[4][8];
#pragma unroll
    for (int i = 0; i < 4; i++)
#pragma unroll
        for (int j = 0; j < 8; j++) acc[i][j] = 0.f;

    const float* xb = x + (size_t)b * 256 * LLEN;

    for (int c0 = 0; c0 < 256; c0 += 8) {
        // load weights: Ws[o][c*13+t] = w[(o0+o)*256*13 + (c0)*13 + r]
        for (int i = tid; i < 64 * 8 * KSZ; i += 256) {
            int o = i / (8 * KSZ);
            int r = i - o * (8 * KSZ);
            Ws[o][r] = w[(size_t)(o0 + o) * 256 * KSZ + (size_t)c0 * KSZ + r];
        }
        // load inputs with halo + zero padding
        for (int i = tid; i < 8 * 140; i += 256) {
            int c = i / 140;
            int j = i - c * 140;
            int l = l0 + j - PADC;
            Xs[c][j] = (l >= 0 && l < LLEN) ? xb[(size_t)(c0 + c) * LLEN + l] : 0.f;
        }
        __syncthreads();

#pragma unroll
        for (int c = 0; c < 8; ++c) {
#pragma unroll
            for (int t = 0; t < KSZ; ++t) {
                float wv[4], xv[8];
#pragma unroll
                for (int i = 0; i < 4; i++) wv[i] = Ws[to + 16 * i][c * KSZ + t];
#pragma unroll
                for (int j = 0; j < 8; j++) xv[j] = Xs[c][tl + 16 * j + t];
#pragma unroll
                for (int i = 0; i < 4; i++)
#pragma unroll
                    for (int j = 0; j < 8; j++) acc[i][j] += wv[i] * xv[j];
            }
        }
        __syncthreads();
    }

#pragma unroll
    for (int i = 0; i < 4; i++) {
        const int o = o0 + to + 16 * i;
        const float bi = bias[o];
        float* yr = y + ((size_t)b * 256 + o) * LLEN + l0;
#pragma unroll
        for (int j = 0; j < 8; j++) yr[tl + 16 * j] = acc[i][j] + bi;
    }
}

// ---------------------------------------------------------------------------
// gemm_nn: C = A * B  (A row-major MxK, B row-major KxN), batched over grid.z.
// Tiles 128x128, K-chunk 16, 256 threads, 8x8 micro-tile.
// Batch offsets: z1 = z / Z2, z2 = z % Z2; off = z1*?1 + z2*?2.
// ---------------------------------------------------------------------------
__global__ __launch_bounds__(256) void gemm_nn_k(
    const float* __restrict__ A, const float* __restrict__ B, float* __restrict__ C,
    int K, int lda, int ldb, int ldc, int Z2,
    long a1, long a2, long b1, long b2, long c1, long c2)
{
    const int z  = blockIdx.z;
    const int z1 = z / Z2, z2 = z - z1 * Z2;
    A += (size_t)(z1 * a1 + z2 * a2);
    B += (size_t)(z1 * b1 + z2 * b2);
    C += (size_t)(z1 * c1 + z2 * c2);

    const int m0 = blockIdx.y * 128;
    const int n0 = blockIdx.x * 128;

    __shared__ __align__(16) float As[16][132];   // [k][m] with pad
    __shared__ __align__(16) float Bs[16][128];   // [k][n]

    const int tid = threadIdx.x;
    const int tm  = tid & 15;
    const int tn  = tid >> 4;

    float acc[8][8];
#pragma unroll
    for (int i = 0; i < 8; i++)
#pragma unroll
        for (int j = 0; j < 8; j++) acc[i][j] = 0.f;

    for (int k0 = 0; k0 < K; k0 += 16) {
        // A tile: 128 rows x 16 k, stored transposed [k][m]
#pragma unroll
        for (int i = tid; i < 128 * 16; i += 256) {
            int r = i >> 4, c = i & 15;
            As[c][r] = A[(size_t)(m0 + r) * lda + k0 + c];
        }
        // B tile: 16 rows x 128 n, float4
#pragma unroll
        for (int i = tid; i < 16 * 32; i += 256) {
            int r = i >> 5, c4 = (i & 31) << 2;
            *(float4*)&Bs[r][c4] = *(const float4*)&B[(size_t)(k0 + r) * ldb + n0 + c4];
        }
        __syncthreads();

#pragma unroll
        for (int kk = 0; kk < 16; ++kk) {
            float a[8], bb[8];
#pragma unroll
            for (int i = 0; i < 8; i++) a[i] = As[kk][tm + 16 * i];
#pragma unroll
            for (int j = 0; j < 8; j++) bb[j] = Bs[kk][tn + 16 * j];
#pragma unroll
            for (int i = 0; i < 8; i++)
#pragma unroll
                for (int j = 0; j < 8; j++) acc[i][j] += a[i] * bb[j];
        }
        __syncthreads();
    }

#pragma unroll
    for (int i = 0; i < 8; i++) {
        float* cr = C + (size_t)(m0 + tm + 16 * i) * ldc + n0;
#pragma unroll
        for (int j = 0; j < 8; j++) cr[tn + 16 * j] = acc[i][j];
    }
}

// ---------------------------------------------------------------------------
// gemm_nt: C = alpha * A * B^T + bias   (A: MxK row-major, B: NxK row-major)
// Both operands K-contiguous. Tiles 128x128, K-chunk 16.
// ---------------------------------------------------------------------------
__global__ __launch_bounds__(256) void gemm_nt_k(
    const float* __restrict__ A, const float* __restrict__ B, float* __restrict__ C,
    int K, int lda, int ldb, int ldc, int Z2,
    long a1, long a2, long b1, long b2, long c1, long c2,
    float alpha, const float* __restrict__ bias)
{
    const int z  = blockIdx.z;
    const int z1 = z / Z2, z2 = z - z1 * Z2;
    A += (size_t)(z1 * a1 + z2 * a2);
    B += (size_t)(z1 * b1 + z2 * b2);
    C += (size_t)(z1 * c1 + z2 * c2);

    const int m0 = blockIdx.y * 128;
    const int n0 = blockIdx.x * 128;

    __shared__ __align__(16) float As[128][17];
    __shared__ __align__(16) float Bs[128][17];

    const int tid = threadIdx.x;
    const int tm  = tid & 15;
    const int tn  = tid >> 4;

    float acc[8][8];
#pragma unroll
    for (int i = 0; i < 8; i++)
#pragma unroll
        for (int j = 0; j < 8; j++) acc[i][j] = 0.f;

    for (int k0 = 0; k0 < K; k0 += 16) {
#pragma unroll
        for (int i = tid; i < 128 * 16; i += 256) {
            int r = i >> 4, c = i & 15;
            As[r][c] = A[(size_t)(m0 + r) * lda + k0 + c];
        }
#pragma unroll
        for (int i = tid; i < 128 * 16; i += 256) {
            int r = i >> 4, c = i & 15;
            Bs[r][c] = B[(size_t)(n0 + r) * ldb + k0 + c];
        }
        __syncthreads();

#pragma unroll
        for (int kk = 0; kk < 16; ++kk) {
            float a[8], bb[8];
#pragma unroll
            for (int i = 0; i < 8; i++) a[i] = As[tm + 16 * i][kk];
#pragma unroll
            for (int j = 0; j < 8; j++) bb[j] = Bs[tn + 16 * j][kk];
#pragma unroll
            for (int i = 0; i < 8; i++)
#pragma unroll
                for (int j = 0; j < 8; j++) acc[i][j] += a[i] * bb[j];
        }
        __syncthreads();
    }

#pragma unroll
    for (int i = 0; i < 8; i++) {
        float* cr = C + (size_t)(m0 + tm + 16 * i) * ldc + n0;
#pragma unroll
        for (int j = 0; j < 8; j++) {
            float bv = bias ? bias[n0 + tn + 16 * j] : 0.f;
            cr[tn + 16 * j] = alpha * acc[i][j] + bv;
        }
    }
}

// ---------------------------------------------------------------------------
// softmax over last axis (256). One warp per row; 8 rows per block.
// ---------------------------------------------------------------------------
__global__ __launch_bounds__(256) void softmax_kernel(
    const float* __restrict__ scores, float* __restrict__ attn)
{
    const int row  = blockIdx.x * 8 + (threadIdx.x >> 5);
    const int lane = threadIdx.x & 31;
    const float* s = scores + (size_t)row * 256;

    float v[8];
    float mx = -1e30f;
#pragma unroll
    for (int j = 0; j < 8; j++) { v[j] = s[lane + 32 * j]; mx = fmaxf(mx, v[j]); }
#pragma unroll
    for (int o = 16; o; o >>= 1) mx = fmaxf(mx, __shfl_xor_sync(0xffffffffu, mx, o));

    float sum = 0.f;
#pragma unroll
    for (int j = 0; j < 8; j++) { v[j] = expf(v[j] - mx); sum += v[j]; }
#pragma unroll
    for (int o = 16; o; o >>= 1) sum += __shfl_xor_sync(0xffffffffu, sum, o);

    const float inv = 1.f / sum;
    float* a = attn + (size_t)row * 256;
#pragma unroll
    for (int j = 0; j < 8; j++) a[lane + 32 * j] = v[j] * inv;
}

// ---------------------------------------------------------------------------
// residual + LayerNorm (ddof=1, eps added to sigma). Row = 1024, one block/row.
// ---------------------------------------------------------------------------
__global__ __launch_bounds__(256) void ln_kernel(
    const float* __restrict__ fc, const float* __restrict__ q,
    const float* __restrict__ ga, const float* __restrict__ gb,
    float* __restrict__ out)
{
    const int row = blockIdx.x;
    const float* f  = fc + (size_t)row * DMODEL;
    const float* qq = q  + (size_t)row * DMODEL;
    const int tid = threadIdx.x;

    float zv[4];
    float s = 0.f, ss = 0.f;
#pragma unroll
    for (int j = 0; j < 4; j++) {
        float zz = f[tid + 256 * j] + qq[tid + 256 * j];
        zv[j] = zz; s += zz; ss += zz * zz;
    }

    __shared__ float rs[8], rss[8];
#pragma unroll
    for (int o = 16; o; o >>= 1) {
        s  += __shfl_xor_sync(0xffffffffu, s, o);
        ss += __shfl_xor_sync(0xffffffffu, ss, o);
    }
    if ((tid & 31) == 0) { rs[tid >> 5] = s; rss[tid >> 5] = ss; }
    __syncthreads();
    if (tid < 32) {
        float a = (tid < 8) ? rs[tid] : 0.f;
        float b = (tid < 8) ? rss[tid] : 0.f;
#pragma unroll
        for (int o = 4; o; o >>= 1) {
            a += __shfl_xor_sync(0xffffffffu, a, o);
            b += __shfl_xor_sync(0xffffffffu, b, o);
        }
        if (tid == 0) { rs[0] = a; rss[0] = b; }
    }
    __syncthreads();

    const float mu  = rs[0] * (1.f / DMODEL);
    const float var = (rss[0] - (float)DMODEL * mu * mu) * (1.f / (DMODEL - 1));
    const float inv = 1.f / (sqrtf(fmaxf(var, 0.f)) + 1e-3f);

    float* o_ = out + (size_t)row * DMODEL;
#pragma unroll
    for (int j = 0; j < 4; j++) {
        const int col = tid + 256 * j;
        o_[col] = (zv[j] - mu) * inv * ga[col] + gb[col];
    }
}

// ---------------------------------------------------------------------------
extern "C" void kernel_launch(void* const* d_in, const int* in_sizes, int n_in,
                              void* d_out, int out_size)
{
    const float* q    = (const float*)d_in[0];
    const float* k    = (const float*)d_in[1];
    const float* v    = (const float*)d_in[2];
    const float* cq_w = (const float*)d_in[3];
    const float* cq_b = (const float*)d_in[4];
    const float* ck_w = (const float*)d_in[5];
    const float* ck_b = (const float*)d_in[6];
    const float* cv_w = (const float*)d_in[7];
    const float* cv_b = (const float*)d_in[8];
    const float* w_qs = (const float*)d_in[9];
    const float* w_ks = (const float*)d_in[10];
    const float* w_vs = (const float*)d_in[11];
    const float* pj_w = (const float*)d_in[12];
    const float* pj_b = (const float*)d_in[13];
    const float* fc_w = (const float*)d_in[14];
    const float* fc_b = (const float*)d_in[15];
    const float* ln_a = (const float*)d_in[16];
    const float* ln_b = (const float*)d_in[17];

    float* ws = nullptr;
    cudaGetSymbolAddress((void**)&ws, g_ws);
    float* qb  = ws + OFF_QB;
    float* kb  = ws + OFF_KB;
    float* vb  = ws + OFF_VB;
    float* qs  = ws + OFF_QS;
    float* ks_ = ws + OFF_KS;
    float* vs  = ws + OFF_VS;
    float* sc  = ws + OFF_SC;
    float* cat = ws + OFF_CAT;
    float* pr  = ws + OFF_PR;
    float* fc  = ws + OFF_FC;

    float* out  = (float*)d_out;
    float* attn = out + (size_t)BATCH * DT * LLEN;   // attns region of d_out

    const dim3 cgrid(LLEN / 128, DT / 64, BATCH);

    // 1. conv1d "projections"
    conv1d_kernel<<<cgrid, 256>>>(q, cq_w, cq_b, qb);
    conv1d_kernel<<<cgrid, 256>>>(k, ck_w, ck_b, kb);
    conv1d_kernel<<<cgrid, 256>>>(v, cv_w, cv_b, vb);

    // 2. per-head projections: qs[h,b] = qb[b] (256x1024) * w_qs[h] (1024x256)
    // z = h*32 + b
    const dim3 ghb(2, 2, NHEAD * BATCH);
    gemm_nn_k<<<ghb, 256>>>(qb, w_qs, qs, 1024, 1024, 256, 256, 32,
                            0, (long)DT * LLEN, (long)LLEN * DT, 0,
                            32L * 65536, 65536);
    gemm_nn_k<<<ghb, 256>>>(kb, w_ks, ks_, 1024, 1024, 256, 256, 32,
                            0, (long)DT * LLEN, (long)LLEN * DT, 0,
                            32L * 65536, 65536);
    gemm_nn_k<<<ghb, 256>>>(vb, w_vs, vs, 1024, 1024, 256, 256, 32,
                            0, (long)DT * LLEN, (long)LLEN * DT, 0,
                            32L * 65536, 65536);

    // 3. scores = qs * ks^T / sqrt(1024)
    gemm_nt_k<<<ghb, 256>>>(qs, ks_, sc, 256, 256, 256, 256, 1,
                            65536, 0, 65536, 0, 65536, 0,
                            1.f / 32.f, nullptr);

    // 4. softmax -> attns output region (layout (H*B, 256, 256) matches)
    softmax_kernel<<<(NHEAD * BATCH * DT) / 8, 256>>>(sc, attn);

    // 5. out = attn * vs, written directly into concat layout (B, 256, H*256)
    gemm_nn_k<<<ghb, 256>>>(attn, vs, cat, 256, 256, 256, NHEAD * DT, 32,
                            32L * 65536, 65536, 32L * 65536, 65536,
                            256, (long)DT * NHEAD * DT);

    // 6. proj: (B,256,2048) @ proj_w^T (+ bias) -> (B,256,1024)   [NT GEMM]
    const dim3 gproj(DMODEL / 128, DT / 128, BATCH);
    gemm_nt_k<<<gproj, 256>>>(cat, pj_w, pr, NHEAD * DT,
                              NHEAD * DT, NHEAD * DT, DMODEL, 1,
                              (long)DT * NHEAD * DT, 0, 0, 0,
                              (long)DT * DMODEL, 0,
                              1.f, pj_b);

    // 7. fc conv1d
    conv1d_kernel<<<cgrid, 256>>>(pr, fc_w, fc_b, fc);

    // 8. residual + LayerNorm -> output region of d_out
    ln_kernel<<<BATCH * DT, 256>>>(fc, q, ln_a, ln_b, out);

    (void)in_sizes; (void)n_in; (void)out_size;
}

// round 11
// speedup vs baseline: 2.4274x; 2.4274x over previous
#include <cuda_runtime.h>
#include <cuda_bf16.h>
#include <math.h>

typedef __nv_bfloat16 bf16;
typedef long long ll;

#define NHEAD  8
#define DMODEL 1024
#define DT     256
#define BATCH  32
#define LLEN   1024

// ---------------------------------------------------------------------------
// Static arenas. hi/lo bf16 twins share offsets.
// ---------------------------------------------------------------------------
#define O_QT   0LL            // (32, 1036, 256) padded transposed inputs
#define O_KT   8486912LL
#define O_VT   16973824LL
#define O_PRT  25460736LL     // (32, 1036, 256) proj output, transposed+padded
#define O_WCQ  33947648LL     // conv weights repacked (13, 256, 256)
#define O_WCK  34799616LL
#define O_WCV  35651584LL
#define O_WFC  36503552LL
#define O_WQT  37355520LL     // head weights transposed (8, 256, 1024)
#define O_WKT  39452672LL
#define O_WVT  41549824LL
#define O_PJW  43646976LL     // proj weight (1024, 2048) split only
#define O_QB   45744128LL     // conv outputs (32, 256, 1024)
#define O_KB   54132736LL
#define O_VB   62521344LL
#define O_QS   70909952LL     // (8, 32, 256, 256)
#define O_KS   87687168LL
#define O_VST  104464384LL    // vs transposed (8, 32, 256(d), 256(t))
#define O_ATT  121241600LL
#define O_CAT  138018816LL    // (32, 256, 2048)
#define BF_TOTAL 154796032LL

#define F_SC   0LL
#define F_FC   16777216LL
#define F_TOTAL 25165824LL

__device__ __align__(1024) bf16  g_bh[BF_TOTAL];
__device__ __align__(1024) bf16  g_bl[BF_TOTAL];
__device__ __align__(1024) float g_fs[F_TOTAL];

// ---------------------------------------------------------------------------
// helpers (all plain sm_80+ PTX: cp.async, ldmatrix, mma.sync)
// ---------------------------------------------------------------------------
__device__ __forceinline__ unsigned smem_u32(const void* p) {
    unsigned a;
    asm("{ .reg .u64 t; cvta.to.shared.u64 t, %1; cvt.u32.u64 %0, t; }"
        : "=r"(a) : "l"(p));
    return a;
}
__device__ __forceinline__ void cp16(unsigned dst, const void* src) {
    asm volatile("cp.async.cg.shared.global [%0], [%1], 16;"
                 :: "r"(dst), "l"(src) : "memory");
}
__device__ __forceinline__ void cp_commit() {
    asm volatile("cp.async.commit_group;" ::: "memory");
}
template <int N>
__device__ __forceinline__ void cp_wait() {
    asm volatile("cp.async.wait_group %0;" :: "n"(N) : "memory");
}
__device__ __forceinline__ void ldsm4(unsigned r[4], unsigned addr) {
    asm volatile("ldmatrix.sync.aligned.m8n8.x4.shared.b16 {%0,%1,%2,%3}, [%4];"
                 : "=r"(r[0]), "=r"(r[1]), "=r"(r[2]), "=r"(r[3]) : "r"(addr));
}
__device__ __forceinline__ void mma16816(float* c, const unsigned a[4],
                                         unsigned b0, unsigned b1) {
    asm volatile(
        "mma.sync.aligned.m16n8k16.row.col.f32.bf16.bf16.f32 "
        "{%0,%1,%2,%3}, {%4,%5,%6,%7}, {%8,%9}, {%0,%1,%2,%3};"
        : "+f"(c[0]), "+f"(c[1]), "+f"(c[2]), "+f"(c[3])
        : "r"(a[0]), "r"(a[1]), "r"(a[2]), "r"(a[3]), "r"(b0), "r"(b1));
}
__device__ __forceinline__ void split2(float x, bf16& h, bf16& l) {
    h = __float2bfloat16(x);
    l = __float2bfloat16(x - __bfloat162float(h));
}

// ---------------------------------------------------------------------------
// Universal split-bf16 NT GEMM with taps (mma.sync path):
//   C[m,n] = alpha * sum_t sum_k A[t][m,k] * B[t][n,k] + bias_m[m]
// A,B: hi/lo bf16 pairs, K-contiguous. CTA tile 128x128, K-chunk 32.
// smem per stage: 4 sub-tiles (Ahi,Alo,Bhi,Blo), each 128 rows x 80B = 10240B.
// 2 stages => 81920 B dynamic smem. 256 threads = 8 warps (4m x 2n),
// warp tile 32(m) x 64(n), fragments m16n8k16.
// ---------------------------------------------------------------------------
#define STG   40960        // bytes per stage
#define SUBT  10240        // bytes per sub-tile
#define GSMEM (2 * STG)

__global__ __launch_bounds__(256, 1)
void gemm_tc(
    const bf16* __restrict__ Ahi, const bf16* __restrict__ Alo,
    const bf16* __restrict__ Bhi, const bf16* __restrict__ Blo,
    float* __restrict__ Cf, bf16* __restrict__ Chi, bf16* __restrict__ Clo,
    int lda, int ldb, int ldc,
    ll a1, ll a2, ll b1, ll b2, ll c1, ll c2,
    ll a_tap, ll b_tap, int kc_per_tap, int taps, int Z2,
    float alpha, const float* __restrict__ bias_m)
{
    extern __shared__ __align__(128) char smem[];
    const unsigned sb0 = smem_u32(smem);
    const int tid = threadIdx.x;
    const int warp = tid >> 5, lane = tid & 31;
    const int z = blockIdx.z, z1 = z / Z2, z2 = z - z1 * Z2;
    const int m0 = blockIdx.y * 128, n0 = blockIdx.x * 128;

    const bf16* pAh = Ahi + (ll)z1 * a1 + (ll)z2 * a2 + (ll)m0 * lda;
    const bf16* pAl = Alo + (ll)z1 * a1 + (ll)z2 * a2 + (ll)m0 * lda;
    const bf16* pBh = Bhi + (ll)z1 * b1 + (ll)z2 * b2 + (ll)n0 * ldb;
    const bf16* pBl = Blo + (ll)z1 * b1 + (ll)z2 * b2 + (ll)n0 * ldb;

    // per-thread cp.async indices: 512 x 16B chunks per sub-tile
    const int ld_row = tid >> 2;          // 0..63  (+64 on second pass)
    const int ld_c16 = tid & 3;           // 16B column within 64B row
    const unsigned ld_off0 = (unsigned)(ld_row * 80 + ld_c16 * 16);
    const unsigned ld_off1 = (unsigned)((ld_row + 64) * 80 + ld_c16 * 16);

    float acc[2][8][4];
#pragma unroll
    for (int a = 0; a < 2; a++)
#pragma unroll
        for (int b = 0; b < 8; b++)
#pragma unroll
            for (int c = 0; c < 4; c++) acc[a][b][c] = 0.f;

    const int NC = kc_per_tap * taps;

    // ---- issue loads for chunk i into stage (i&1) ----
    auto issue = [&](int i) {
        const int t  = (taps == 1) ? 0 : (i / kc_per_tap);
        const int kc = i - t * kc_per_tap;
        const ll ao = (ll)t * a_tap + (ll)kc * 32 + (ll)ld_c16 * 8;
        const ll bo = (ll)t * b_tap + (ll)kc * 32 + (ll)ld_c16 * 8;
        const unsigned s = sb0 + (i & 1) * STG;
        const ll ar0 = (ll)ld_row * lda, ar1 = (ll)(ld_row + 64) * lda;
        const ll br0 = (ll)ld_row * ldb, br1 = (ll)(ld_row + 64) * ldb;
        cp16(s + ld_off0,             pAh + ao + ar0);
        cp16(s + ld_off1,             pAh + ao + ar1);
        cp16(s + SUBT + ld_off0,      pAl + ao + ar0);
        cp16(s + SUBT + ld_off1,      pAl + ao + ar1);
        cp16(s + 2 * SUBT + ld_off0,  pBh + bo + br0);
        cp16(s + 2 * SUBT + ld_off1,  pBh + bo + br1);
        cp16(s + 3 * SUBT + ld_off0,  pBl + bo + br0);
        cp16(s + 3 * SUBT + ld_off1,  pBl + bo + br1);
        cp_commit();
    };

    const int wm = (warp & 3) * 32;       // warp m origin in tile
    const int wn = (warp >> 2) * 64;      // warp n origin
    const int li = lane & 7, lj = lane >> 3;
    // ldmatrix per-lane address pieces (A: j0/j1 rows +0/+8 k0; j2/j3 k+8)
    const int a_row_add = li + ((lj & 1) << 3);
    const unsigned a_col = (unsigned)((lj >> 1) << 4);
    // B: j0/j1 k0/k+8 rows +0; j2/j3 rows +8
    const int b_row_add = li + ((lj >> 1) << 3);
    const unsigned b_col = (unsigned)((lj & 1) << 4);

    issue(0);
    for (int i = 0; i < NC; i++) {
        if (i + 1 < NC) { issue(i + 1); cp_wait<1>(); }
        else            { cp_wait<0>(); }
        __syncthreads();

        const unsigned s = sb0 + (i & 1) * STG;
#pragma unroll
        for (int kk = 0; kk < 2; kk++) {
            unsigned ah[2][4], al[2][4];
#pragma unroll
            for (int mb = 0; mb < 2; mb++) {
                const unsigned ar = (unsigned)((wm + mb * 16 + a_row_add) * 80)
                                    + (unsigned)(kk * 32) + a_col;
                ldsm4(ah[mb], s + ar);
                ldsm4(al[mb], s + SUBT + ar);
            }
#pragma unroll
            for (int nb = 0; nb < 4; nb++) {
                const unsigned br = (unsigned)((wn + nb * 16 + b_row_add) * 80)
                                    + (unsigned)(kk * 32) + b_col;
                unsigned bh[4], blr[4];
                ldsm4(bh,  s + 2 * SUBT + br);
                ldsm4(blr, s + 3 * SUBT + br);
#pragma unroll
                for (int mb = 0; mb < 2; mb++) {
#pragma unroll
                    for (int h = 0; h < 2; h++) {
                        float* c = acc[mb][nb * 2 + h];
                        mma16816(c, ah[mb], bh[2 * h],  bh[2 * h + 1]);
                        mma16816(c, ah[mb], blr[2 * h], blr[2 * h + 1]);
                        mma16816(c, al[mb], bh[2 * h],  bh[2 * h + 1]);
                    }
                }
            }
        }
        __syncthreads();
    }

    // ---- epilogue ----
    const ll coff = (ll)z1 * c1 + (ll)z2 * c2;
    const int g = lane >> 2, qd = lane & 3;
#pragma unroll
    for (int mb = 0; mb < 2; mb++) {
        const int r0 = m0 + wm + mb * 16 + g;
        const float bm0 = bias_m ? bias_m[r0] : 0.f;
        const float bm1 = bias_m ? bias_m[r0 + 8] : 0.f;
#pragma unroll
        for (int nf = 0; nf < 8; nf++) {
            const int col = n0 + wn + nf * 8 + qd * 2;
            const float* c = acc[mb][nf];
            float v00 = c[0] * alpha + bm0, v01 = c[1] * alpha + bm0;
            float v10 = c[2] * alpha + bm1, v11 = c[3] * alpha + bm1;
            const ll o0 = coff + (ll)r0 * ldc + col;
            const ll o1 = coff + (ll)(r0 + 8) * ldc + col;
            if (Cf) {
                *reinterpret_cast<float2*>(Cf + o0) = make_float2(v00, v01);
                *reinterpret_cast<float2*>(Cf + o1) = make_float2(v10, v11);
            }
            if (Chi) {
                bf16 h0, l0, h1, l1;
                split2(v00, h0, l0); split2(v01, h1, l1);
                *reinterpret_cast<__nv_bfloat162*>(Chi + o0) = __nv_bfloat162(h0, h1);
                *reinterpret_cast<__nv_bfloat162*>(Clo + o0) = __nv_bfloat162(l0, l1);
                split2(v10, h0, l0); split2(v11, h1, l1);
                *reinterpret_cast<__nv_bfloat162*>(Chi + o1) = __nv_bfloat162(h0, h1);
                *reinterpret_cast<__nv_bfloat162*>(Clo + o1) = __nv_bfloat162(l0, l1);
            }
        }
    }
}

// ---------------------------------------------------------------------------
// Prep: transpose + split.  in (Z,R,C) fp32 -> out[z][(c+row0)*R + r] hi/lo
// ---------------------------------------------------------------------------
__global__ __launch_bounds__(256) void transpose_split(
    const float* __restrict__ in, bf16* __restrict__ oh, bf16* __restrict__ ol,
    int R, int C, ll in_z, ll out_z, int row0)
{
    __shared__ float t[32][33];
    const int z = blockIdx.z;
    const int c0 = blockIdx.x * 32, r0 = blockIdx.y * 32;
    const int tx = threadIdx.x & 31, ty = threadIdx.x >> 5;
    const float* ip = in + (size_t)z * in_z;
#pragma unroll
    for (int j = 0; j < 4; j++)
        t[ty + 8 * j][tx] = ip[(size_t)(r0 + ty + 8 * j) * C + c0 + tx];
    __syncthreads();
    bf16* hp = oh + (size_t)z * out_z;
    bf16* lp = ol + (size_t)z * out_z;
#pragma unroll
    for (int j = 0; j < 4; j++) {
        float v = t[tx][ty + 8 * j];
        bf16 h, l; split2(v, h, l);
        size_t o = (size_t)(c0 + ty + 8 * j + row0) * R + r0 + tx;
        hp[o] = h; lp[o] = l;
    }
}

__global__ __launch_bounds__(256) void split_k(
    const float* __restrict__ in, bf16* __restrict__ oh, bf16* __restrict__ ol, int n)
{
    int i = blockIdx.x * 256 + threadIdx.x;
    if (i < n) { bf16 h, l; split2(in[i], h, l); oh[i] = h; ol[i] = l; }
}

// conv weight repack: out[t][o][c] = w[o][c][t], split.
__global__ __launch_bounds__(256) void conv_w_prep(
    const float* __restrict__ w, bf16* __restrict__ oh, bf16* __restrict__ ol)
{
    int idx = blockIdx.x * 256 + threadIdx.x;          // < 851968
    int t = idx >> 16, rem = idx & 65535;
    int o = rem >> 8, c = rem & 255;
    float x = w[(size_t)(o * 256 + c) * 13 + t];
    bf16 h, l; split2(x, h, l);
    oh[idx] = h; ol[idx] = l;
}

// zero the 12 halo pad rows of a (32, 1036, 256) transposed array (hi+lo)
__global__ __launch_bounds__(256) void zero_pads(bf16* __restrict__ ph,
                                                 bf16* __restrict__ pl)
{
    int idx = blockIdx.x * 256 + threadIdx.x;          // < 98304
    int b = idx / 3072, rem = idx % 3072;
    int r12 = rem >> 8, c = rem & 255;
    int row = (r12 < 6) ? r12 : (1024 + r12);
    size_t o = (size_t)b * 265216 + (size_t)row * 256 + c;
    ph[o] = __float2bfloat16(0.f);
    pl[o] = __float2bfloat16(0.f);
}

// ---------------------------------------------------------------------------
// softmax over last axis (256); fp32 attn to d_out AND split pair to arena.
// ---------------------------------------------------------------------------
__global__ __launch_bounds__(256) void softmax_split(
    const float* __restrict__ scores, float* __restrict__ attn,
    bf16* __restrict__ ah, bf16* __restrict__ al)
{
    const int row  = blockIdx.x * 8 + (threadIdx.x >> 5);
    const int lane = threadIdx.x & 31;
    const float* s = scores + (size_t)row * 256;

    float v[8];
    float mx = -1e30f;
#pragma unroll
    for (int j = 0; j < 8; j++) { v[j] = s[lane + 32 * j]; mx = fmaxf(mx, v[j]); }
#pragma unroll
    for (int o = 16; o; o >>= 1) mx = fmaxf(mx, __shfl_xor_sync(0xffffffffu, mx, o));
    float sum = 0.f;
#pragma unroll
    for (int j = 0; j < 8; j++) { v[j] = expf(v[j] - mx); sum += v[j]; }
#pragma unroll
    for (int o = 16; o; o >>= 1) sum += __shfl_xor_sync(0xffffffffu, sum, o);
    const float inv = 1.f / sum;

    float* a  = attn + (size_t)row * 256;
    bf16* hh = ah + (size_t)row * 256;
    bf16* ll_ = al + (size_t)row * 256;
#pragma unroll
    for (int j = 0; j < 8; j++) {
        float p = v[j] * inv;
        a[lane + 32 * j] = p;
        bf16 h, l; split2(p, h, l);
        hh[lane + 32 * j] = h; ll_[lane + 32 * j] = l;
    }
}

// ---------------------------------------------------------------------------
// residual + LayerNorm (ddof=1, eps added to sigma)
// ---------------------------------------------------------------------------
__global__ __launch_bounds__(256) void ln_kernel(
    const float* __restrict__ fc, const float* __restrict__ q,
    const float* __restrict__ ga, const float* __restrict__ gb,
    float* __restrict__ out)
{
    const int row = blockIdx.x;
    const float* f  = fc + (size_t)row * DMODEL;
    const float* qq = q  + (size_t)row * DMODEL;
    const int tid = threadIdx.x;

    float zv[4];
    float s = 0.f, ss = 0.f;
#pragma unroll
    for (int j = 0; j < 4; j++) {
        float zz = f[tid + 256 * j] + qq[tid + 256 * j];
        zv[j] = zz; s += zz; ss += zz * zz;
    }
    __shared__ float rs[8], rss[8];
#pragma unroll
    for (int o = 16; o; o >>= 1) {
        s  += __shfl_xor_sync(0xffffffffu, s, o);
        ss += __shfl_xor_sync(0xffffffffu, ss, o);
    }
    if ((tid & 31) == 0) { rs[tid >> 5] = s; rss[tid >> 5] = ss; }
    __syncthreads();
    if (tid < 32) {
        float a = (tid < 8) ? rs[tid] : 0.f;
        float b = (tid < 8) ? rss[tid] : 0.f;
#pragma unroll
        for (int o = 4; o; o >>= 1) {
            a += __shfl_xor_sync(0xffffffffu, a, o);
            b += __shfl_xor_sync(0xffffffffu, b, o);
        }
        if (tid == 0) { rs[0] = a; rss[0] = b; }
    }
    __syncthreads();
    const float mu  = rs[0] * (1.f / DMODEL);
    const float var = (rss[0] - (float)DMODEL * mu * mu) * (1.f / (DMODEL - 1));
    const float inv = 1.f / (sqrtf(fmaxf(var, 0.f)) + 1e-3f);
    float* o_ = out + (size_t)row * DMODEL;
#pragma unroll
    for (int j = 0; j < 4; j++) {
        const int col = tid + 256 * j;
        o_[col] = (zv[j] - mu) * inv * ga[col] + gb[col];
    }
}

// ---------------------------------------------------------------------------
extern "C" void kernel_launch(void* const* d_in, const int* in_sizes, int n_in,
                              void* d_out, int out_size)
{
    const float* q    = (const float*)d_in[0];
    const float* k    = (const float*)d_in[1];
    const float* v    = (const float*)d_in[2];
    const float* cq_w = (const float*)d_in[3];
    const float* cq_b = (const float*)d_in[4];
    const float* ck_w = (const float*)d_in[5];
    const float* ck_b = (const float*)d_in[6];
    const float* cv_w = (const float*)d_in[7];
    const float* cv_b = (const float*)d_in[8];
    const float* w_qs = (const float*)d_in[9];
    const float* w_ks = (const float*)d_in[10];
    const float* w_vs = (const float*)d_in[11];
    const float* pj_w = (const float*)d_in[12];
    const float* pj_b = (const float*)d_in[13];
    const float* fc_w = (const float*)d_in[14];
    const float* fc_b = (const float*)d_in[15];
    const float* ln_a = (const float*)d_in[16];
    const float* ln_b = (const float*)d_in[17];

    bf16 *bh = nullptr, *bl = nullptr; float* fs = nullptr;
    cudaGetSymbolAddress((void**)&bh, g_bh);
    cudaGetSymbolAddress((void**)&bl, g_bl);
    cudaGetSymbolAddress((void**)&fs, g_fs);

    cudaFuncSetAttribute(gemm_tc, cudaFuncAttributeMaxDynamicSharedMemorySize, GSMEM);

    float* out  = (float*)d_out;
    float* attn = out + (size_t)BATCH * DT * LLEN;

    // ---- prep ----
    zero_pads<<<384, 256>>>(bh + O_QT,  bl + O_QT);
    zero_pads<<<384, 256>>>(bh + O_KT,  bl + O_KT);
    zero_pads<<<384, 256>>>(bh + O_VT,  bl + O_VT);
    zero_pads<<<384, 256>>>(bh + O_PRT, bl + O_PRT);
    transpose_split<<<dim3(32, 8, 32), 256>>>(q, bh + O_QT, bl + O_QT,
                                              256, 1024, 262144, 265216, 6);
    transpose_split<<<dim3(32, 8, 32), 256>>>(k, bh + O_KT, bl + O_KT,
                                              256, 1024, 262144, 265216, 6);
    transpose_split<<<dim3(32, 8, 32), 256>>>(v, bh + O_VT, bl + O_VT,
                                              256, 1024, 262144, 265216, 6);
    transpose_split<<<dim3(8, 32, 8), 256>>>(w_qs, bh + O_WQT, bl + O_WQT,
                                             1024, 256, 262144, 262144, 0);
    transpose_split<<<dim3(8, 32, 8), 256>>>(w_ks, bh + O_WKT, bl + O_WKT,
                                             1024, 256, 262144, 262144, 0);
    transpose_split<<<dim3(8, 32, 8), 256>>>(w_vs, bh + O_WVT, bl + O_WVT,
                                             1024, 256, 262144, 262144, 0);
    conv_w_prep<<<3328, 256>>>(cq_w, bh + O_WCQ, bl + O_WCQ);
    conv_w_prep<<<3328, 256>>>(ck_w, bh + O_WCK, bl + O_WCK);
    conv_w_prep<<<3328, 256>>>(cv_w, bh + O_WCV, bl + O_WCV);
    conv_w_prep<<<3328, 256>>>(fc_w, bh + O_WFC, bl + O_WFC);
    split_k<<<8192, 256>>>(pj_w, bh + O_PJW, bl + O_PJW, 2097152);

    // ---- 1. conv q/k/v: M=256(o), N=1024(l), K=256 x 13 taps ----
    const dim3 gconv(8, 2, 32);
    gemm_tc<<<gconv, 256, GSMEM>>>(bh + O_WCQ, bl + O_WCQ, bh + O_QT, bl + O_QT,
        nullptr, bh + O_QB, bl + O_QB, 256, 256, 1024,
        0, 0, 0, 265216, 0, 262144, 65536, 256, 8, 13, 32, 1.f, cq_b);
    gemm_tc<<<gconv, 256, GSMEM>>>(bh + O_WCK, bl + O_WCK, bh + O_KT, bl + O_KT,
        nullptr, bh + O_KB, bl + O_KB, 256, 256, 1024,
        0, 0, 0, 265216, 0, 262144, 65536, 256, 8, 13, 32, 1.f, ck_b);
    gemm_tc<<<gconv, 256, GSMEM>>>(bh + O_WCV, bl + O_WCV, bh + O_VT, bl + O_VT,
        nullptr, bh + O_VB, bl + O_VB, 256, 256, 1024,
        0, 0, 0, 265216, 0, 262144, 65536, 256, 8, 13, 32, 1.f, cv_b);

    // ---- 2. head projections (z1 = h, z2 = b) ----
    const dim3 ghb(2, 2, 256);
    gemm_tc<<<ghb, 256, GSMEM>>>(bh + O_QB, bl + O_QB, bh + O_WQT, bl + O_WQT,
        nullptr, bh + O_QS, bl + O_QS, 1024, 1024, 256,
        0, 262144, 262144, 0, 2097152, 65536, 0, 0, 32, 1, 32, 1.f, nullptr);
    gemm_tc<<<ghb, 256, GSMEM>>>(bh + O_KB, bl + O_KB, bh + O_WKT, bl + O_WKT,
        nullptr, bh + O_KS, bl + O_KS, 1024, 1024, 256,
        0, 262144, 262144, 0, 2097152, 65536, 0, 0, 32, 1, 32, 1.f, nullptr);
    gemm_tc<<<ghb, 256, GSMEM>>>(bh + O_WVT, bl + O_WVT, bh + O_VB, bl + O_VB,
        nullptr, bh + O_VST, bl + O_VST, 1024, 1024, 256,
        262144, 0, 0, 262144, 2097152, 65536, 0, 0, 32, 1, 32, 1.f, nullptr);

    // ---- 3. scores = qs . ks^T / 32 -> fp32 ----
    gemm_tc<<<ghb, 256, GSMEM>>>(bh + O_QS, bl + O_QS, bh + O_KS, bl + O_KS,
        fs + F_SC, nullptr, nullptr, 256, 256, 256,
        2097152, 65536, 2097152, 65536, 2097152, 65536, 0, 0, 8, 1, 32,
        1.f / 32.f, nullptr);

    // ---- 4. softmax -> attns (d_out) + split arena ----
    softmax_split<<<8192, 256>>>(fs + F_SC, attn, bh + O_ATT, bl + O_ATT);

    // ---- 5. out = attn . vsT^T -> cat (B, 256, 2048) ----
    gemm_tc<<<ghb, 256, GSMEM>>>(bh + O_ATT, bl + O_ATT, bh + O_VST, bl + O_VST,
        nullptr, bh + O_CAT, bl + O_CAT, 256, 256, 2048,
        2097152, 65536, 2097152, 65536, 256, 524288, 0, 0, 8, 1, 32,
        1.f, nullptr);

    // ---- 6. proj, transposed: C[dm][t] -> prT (pad row offset 6) ----
    gemm_tc<<<dim3(2, 8, 32), 256, GSMEM>>>(bh + O_PJW, bl + O_PJW,
        bh + O_CAT, bl + O_CAT,
        nullptr, bh + O_PRT + 1536, bl + O_PRT + 1536, 2048, 2048, 256,
        0, 0, 0, 524288, 0, 265216, 0, 0, 64, 1, 32, 1.f, pj_b);

    // ---- 7. fc conv: M=256(o), N=1024(l), K=256 x 13 -> fp32 ----
    gemm_tc<<<gconv, 256, GSMEM>>>(bh + O_WFC, bl + O_WFC, bh + O_PRT, bl + O_PRT,
        fs + F_FC, nullptr, nullptr, 256, 256, 1024,
        0, 0, 0, 265216, 0, 262144, 65536, 256, 8, 13, 32, 1.f, fc_b);

    // ---- 8. residual + LayerNorm ----
    ln_kernel<<<BATCH * DT, 256>>>(fs + F_FC, q, ln_a, ln_b, out);

    (void)in_sizes; (void)n_in; (void)out_size;
}

// round 12
// speedup vs baseline: 3.2002x; 1.3183x over previous
#include <cuda_runtime.h>
#include <cuda_bf16.h>
#include <math.h>

typedef __nv_bfloat16 bf16;
typedef long long ll;

#define NHEAD  8
#define DMODEL 1024
#define DT     256
#define BATCH  32
#define LLEN   1024

// ---------------------------------------------------------------------------
// Static arenas. hi/lo bf16 twins share offsets.
// NOTE: QT,KT,VT,PRT are contiguous with uniform stride 8486912 (used by the
// merged zero_pads). WCQ/WCK/WCV uniform stride 851968; QB/KB/VB 8388608.
// ---------------------------------------------------------------------------
#define O_QT   0LL            // (32, 1036, 256) padded transposed inputs
#define O_KT   8486912LL
#define O_VT   16973824LL
#define O_PRT  25460736LL     // (32, 1036, 256) proj output, transposed+padded
#define O_WCQ  33947648LL     // conv weights repacked (13, 256, 256)
#define O_WCK  34799616LL
#define O_WCV  35651584LL
#define O_WFC  36503552LL
#define O_WQT  37355520LL     // head weights transposed (8, 256, 1024)
#define O_WKT  39452672LL
#define O_WVT  41549824LL
#define O_PJW  43646976LL     // proj weight (1024, 2048) split only
#define O_QB   45744128LL     // conv outputs (32, 256, 1024)
#define O_KB   54132736LL
#define O_VB   62521344LL
#define O_QS   70909952LL     // (8, 32, 256, 256)
#define O_KS   87687168LL
#define O_VST  104464384LL    // vs transposed (8, 32, 256(d), 256(t))
#define O_ATT  121241600LL
#define O_CAT  138018816LL    // (32, 256, 2048)
#define BF_TOTAL 154796032LL

#define F_SC   0LL
#define F_FC   16777216LL
#define F_BIAS 25165824LL     // packed conv biases (3 x 256)
#define F_TOTAL 25166848LL

__device__ __align__(1024) bf16  g_bh[BF_TOTAL];
__device__ __align__(1024) bf16  g_bl[BF_TOTAL];
__device__ __align__(1024) float g_fs[F_TOTAL];

// ---------------------------------------------------------------------------
// helpers (all plain sm_80+ PTX: cp.async, ldmatrix, mma.sync)
// ---------------------------------------------------------------------------
__device__ __forceinline__ unsigned smem_u32(const void* p) {
    unsigned a;
    asm("{ .reg .u64 t; cvta.to.shared.u64 t, %1; cvt.u32.u64 %0, t; }"
        : "=r"(a) : "l"(p));
    return a;
}
__device__ __forceinline__ void cp16(unsigned dst, const void* src) {
    asm volatile("cp.async.cg.shared.global [%0], [%1], 16;"
                 :: "r"(dst), "l"(src) : "memory");
}
__device__ __forceinline__ void cp_commit() {
    asm volatile("cp.async.commit_group;" ::: "memory");
}
template <int N>
__device__ __forceinline__ void cp_wait() {
    asm volatile("cp.async.wait_group %0;" :: "n"(N) : "memory");
}
__device__ __forceinline__ void ldsm4(unsigned r[4], unsigned addr) {
    asm volatile("ldmatrix.sync.aligned.m8n8.x4.shared.b16 {%0,%1,%2,%3}, [%4];"
                 : "=r"(r[0]), "=r"(r[1]), "=r"(r[2]), "=r"(r[3]) : "r"(addr));
}
__device__ __forceinline__ void mma16816(float* c, const unsigned a[4],
                                         unsigned b0, unsigned b1) {
    asm volatile(
        "mma.sync.aligned.m16n8k16.row.col.f32.bf16.bf16.f32 "
        "{%0,%1,%2,%3}, {%4,%5,%6,%7}, {%8,%9}, {%0,%1,%2,%3};"
        : "+f"(c[0]), "+f"(c[1]), "+f"(c[2]), "+f"(c[3])
        : "r"(a[0]), "r"(a[1]), "r"(a[2]), "r"(a[3]), "r"(b0), "r"(b1));
}
__device__ __forceinline__ void split2(float x, bf16& h, bf16& l) {
    h = __float2bfloat16(x);
    l = __float2bfloat16(x - __bfloat162float(h));
}

// ---------------------------------------------------------------------------
// Universal split-bf16 NT GEMM with taps (mma.sync path):
//   C[m,n] = alpha * sum_t sum_k A[t][m,k] * B[t][n,k] + bias_m[z1*bias_z + m]
// A,B: hi/lo bf16 pairs, K-contiguous. CTA tile 128x128, K-chunk 32.
// smem per stage: 4 sub-tiles (Ahi,Alo,Bhi,Blo), each 128 rows x 80B = 10240B.
// 2 stages => 81920 B dynamic smem; 2 CTAs/SM. 8 warps (4m x 2n),
// warp tile 32(m) x 64(n), fragments m16n8k16.
// ---------------------------------------------------------------------------
#define STG   40960        // bytes per stage
#define SUBT  10240        // bytes per sub-tile
#define GSMEM (2 * STG)

__global__ __launch_bounds__(256, 2)
void gemm_tc(
    const bf16* __restrict__ Ahi, const bf16* __restrict__ Alo,
    const bf16* __restrict__ Bhi, const bf16* __restrict__ Blo,
    float* __restrict__ Cf, bf16* __restrict__ Chi, bf16* __restrict__ Clo,
    int lda, int ldb, int ldc,
    ll a1, ll a2, ll b1, ll b2, ll c1, ll c2,
    ll a_tap, ll b_tap, int kc_per_tap, int taps, int Z2,
    float alpha, const float* __restrict__ bias_m, ll bias_z)
{
    extern __shared__ __align__(128) char smem[];
    const unsigned sb0 = smem_u32(smem);
    const int tid = threadIdx.x;
    const int warp = tid >> 5, lane = tid & 31;
    const int z = blockIdx.z, z1 = z / Z2, z2 = z - z1 * Z2;
    const int m0 = blockIdx.y * 128, n0 = blockIdx.x * 128;

    const bf16* pAh = Ahi + (ll)z1 * a1 + (ll)z2 * a2 + (ll)m0 * lda;
    const bf16* pAl = Alo + (ll)z1 * a1 + (ll)z2 * a2 + (ll)m0 * lda;
    const bf16* pBh = Bhi + (ll)z1 * b1 + (ll)z2 * b2 + (ll)n0 * ldb;
    const bf16* pBl = Blo + (ll)z1 * b1 + (ll)z2 * b2 + (ll)n0 * ldb;

    // per-thread cp.async indices: 512 x 16B chunks per sub-tile
    const int ld_row = tid >> 2;          // 0..63  (+64 on second pass)
    const int ld_c16 = tid & 3;           // 16B column within 64B row
    const unsigned ld_off0 = (unsigned)(ld_row * 80 + ld_c16 * 16);
    const unsigned ld_off1 = (unsigned)((ld_row + 64) * 80 + ld_c16 * 16);

    float acc[2][8][4];
#pragma unroll
    for (int a = 0; a < 2; a++)
#pragma unroll
        for (int b = 0; b < 8; b++)
#pragma unroll
            for (int c = 0; c < 4; c++) acc[a][b][c] = 0.f;

    const int NC = kc_per_tap * taps;

    // ---- issue loads for chunk i into stage (i&1) ----
    auto issue = [&](int i) {
        const int t  = (taps == 1) ? 0 : (i / kc_per_tap);
        const int kc = i - t * kc_per_tap;
        const ll ao = (ll)t * a_tap + (ll)kc * 32 + (ll)ld_c16 * 8;
        const ll bo = (ll)t * b_tap + (ll)kc * 32 + (ll)ld_c16 * 8;
        const unsigned s = sb0 + (i & 1) * STG;
        const ll ar0 = (ll)ld_row * lda, ar1 = (ll)(ld_row + 64) * lda;
        const ll br0 = (ll)ld_row * ldb, br1 = (ll)(ld_row + 64) * ldb;
        cp16(s + ld_off0,             pAh + ao + ar0);
        cp16(s + ld_off1,             pAh + ao + ar1);
        cp16(s + SUBT + ld_off0,      pAl + ao + ar0);
        cp16(s + SUBT + ld_off1,      pAl + ao + ar1);
        cp16(s + 2 * SUBT + ld_off0,  pBh + bo + br0);
        cp16(s + 2 * SUBT + ld_off1,  pBh + bo + br1);
        cp16(s + 3 * SUBT + ld_off0,  pBl + bo + br0);
        cp16(s + 3 * SUBT + ld_off1,  pBl + bo + br1);
        cp_commit();
    };

    const int wm = (warp & 3) * 32;       // warp m origin in tile
    const int wn = (warp >> 2) * 64;      // warp n origin
    const int li = lane & 7, lj = lane >> 3;
    const int a_row_add = li + ((lj & 1) << 3);
    const unsigned a_col = (unsigned)((lj >> 1) << 4);
    const int b_row_add = li + ((lj >> 1) << 3);
    const unsigned b_col = (unsigned)((lj & 1) << 4);

    issue(0);
    for (int i = 0; i < NC; i++) {
        if (i + 1 < NC) { issue(i + 1); cp_wait<1>(); }
        else            { cp_wait<0>(); }
        __syncthreads();

        const unsigned s = sb0 + (i & 1) * STG;
#pragma unroll
        for (int kk = 0; kk < 2; kk++) {
            unsigned ah[2][4], al[2][4];
#pragma unroll
            for (int mb = 0; mb < 2; mb++) {
                const unsigned ar = (unsigned)((wm + mb * 16 + a_row_add) * 80)
                                    + (unsigned)(kk * 32) + a_col;
                ldsm4(ah[mb], s + ar);
                ldsm4(al[mb], s + SUBT + ar);
            }
#pragma unroll
            for (int nb = 0; nb < 4; nb++) {
                const unsigned br = (unsigned)((wn + nb * 16 + b_row_add) * 80)
                                    + (unsigned)(kk * 32) + b_col;
                unsigned bh[4], blr[4];
                ldsm4(bh,  s + 2 * SUBT + br);
                ldsm4(blr, s + 3 * SUBT + br);
#pragma unroll
                for (int mb = 0; mb < 2; mb++) {
#pragma unroll
                    for (int h = 0; h < 2; h++) {
                        float* c = acc[mb][nb * 2 + h];
                        mma16816(c, ah[mb], bh[2 * h],  bh[2 * h + 1]);
                        mma16816(c, ah[mb], blr[2 * h], blr[2 * h + 1]);
                        mma16816(c, al[mb], bh[2 * h],  bh[2 * h + 1]);
                    }
                }
            }
        }
        __syncthreads();
    }

    // ---- epilogue ----
    const ll coff = (ll)z1 * c1 + (ll)z2 * c2;
    const ll boffb = (ll)z1 * bias_z;
    const int g = lane >> 2, qd = lane & 3;
#pragma unroll
    for (int mb = 0; mb < 2; mb++) {
        const int r0 = m0 + wm + mb * 16 + g;
        const float bm0 = bias_m ? bias_m[boffb + r0] : 0.f;
        const float bm1 = bias_m ? bias_m[boffb + r0 + 8] : 0.f;
#pragma unroll
        for (int nf = 0; nf < 8; nf++) {
            const int col = n0 + wn + nf * 8 + qd * 2;
            const float* c = acc[mb][nf];
            float v00 = c[0] * alpha + bm0, v01 = c[1] * alpha + bm0;
            float v10 = c[2] * alpha + bm1, v11 = c[3] * alpha + bm1;
            const ll o0 = coff + (ll)r0 * ldc + col;
            const ll o1 = coff + (ll)(r0 + 8) * ldc + col;
            if (Cf) {
                *reinterpret_cast<float2*>(Cf + o0) = make_float2(v00, v01);
                *reinterpret_cast<float2*>(Cf + o1) = make_float2(v10, v11);
            }
            if (Chi) {
                bf16 h0, l0, h1, l1;
                split2(v00, h0, l0); split2(v01, h1, l1);
                *reinterpret_cast<__nv_bfloat162*>(Chi + o0) = __nv_bfloat162(h0, h1);
                *reinterpret_cast<__nv_bfloat162*>(Clo + o0) = __nv_bfloat162(l0, l1);
                split2(v10, h0, l0); split2(v11, h1, l1);
                *reinterpret_cast<__nv_bfloat162*>(Chi + o1) = __nv_bfloat162(h0, h1);
                *reinterpret_cast<__nv_bfloat162*>(Clo + o1) = __nv_bfloat162(l0, l1);
            }
        }
    }
}

// ---------------------------------------------------------------------------
// Prep: transpose + split.  in (Z,R,C) fp32 -> out[z][(c+row0)*R + r] hi/lo
// ---------------------------------------------------------------------------
__global__ __launch_bounds__(256) void transpose_split(
    const float* __restrict__ in, bf16* __restrict__ oh, bf16* __restrict__ ol,
    int R, int C, ll in_z, ll out_z, int row0)
{
    __shared__ float t[32][33];
    const int z = blockIdx.z;
    const int c0 = blockIdx.x * 32, r0 = blockIdx.y * 32;
    const int tx = threadIdx.x & 31, ty = threadIdx.x >> 5;
    const float* ip = in + (size_t)z * in_z;
#pragma unroll
    for (int j = 0; j < 4; j++)
        t[ty + 8 * j][tx] = ip[(size_t)(r0 + ty + 8 * j) * C + c0 + tx];
    __syncthreads();
    bf16* hp = oh + (size_t)z * out_z;
    bf16* lp = ol + (size_t)z * out_z;
#pragma unroll
    for (int j = 0; j < 4; j++) {
        float v = t[tx][ty + 8 * j];
        bf16 h, l; split2(v, h, l);
        size_t o = (size_t)(c0 + ty + 8 * j + row0) * R + r0 + tx;
        hp[o] = h; lp[o] = l;
    }
}

__global__ __launch_bounds__(256) void split_k(
    const float* __restrict__ in, bf16* __restrict__ oh, bf16* __restrict__ ol, int n)
{
    int i = blockIdx.x * 256 + threadIdx.x;
    if (i < n) { bf16 h, l; split2(in[i], h, l); oh[i] = h; ol[i] = l; }
}

// conv weight repack: out[t][o][c] = w[o][c][t], split.
__global__ __launch_bounds__(256) void conv_w_prep(
    const float* __restrict__ w, bf16* __restrict__ oh, bf16* __restrict__ ol)
{
    int idx = blockIdx.x * 256 + threadIdx.x;          // < 851968
    int t = idx >> 16, rem = idx & 65535;
    int o = rem >> 8, c = rem & 255;
    float x = w[(size_t)(o * 256 + c) * 13 + t];
    bf16 h, l; split2(x, h, l);
    oh[idx] = h; ol[idx] = l;
}

// zero the 12 halo pad rows of FOUR contiguous (32,1036,256) arrays (hi+lo)
__global__ __launch_bounds__(256) void zero_pads(bf16* __restrict__ ph,
                                                 bf16* __restrict__ pl)
{
    int idx = blockIdx.x * 256 + threadIdx.x;          // < 393216
    int b = idx / 3072, rem = idx % 3072;              // b in 0..127
    int r12 = rem >> 8, c = rem & 255;
    int row = (r12 < 6) ? r12 : (1024 + r12);
    size_t o = (size_t)b * 265216 + (size_t)row * 256 + c;
    ph[o] = __float2bfloat16(0.f);
    pl[o] = __float2bfloat16(0.f);
}

// pack the three conv biases into one strided array
__global__ __launch_bounds__(256) void pack_bias(
    const float* __restrict__ a, const float* __restrict__ b,
    const float* __restrict__ c, float* __restrict__ o)
{
    int i = threadIdx.x;
    o[i] = a[i]; o[256 + i] = b[i]; o[512 + i] = c[i];
}

// ---------------------------------------------------------------------------
// softmax over last axis (256); fp32 attn to d_out AND split pair to arena.
// ---------------------------------------------------------------------------
__global__ __launch_bounds__(256) void softmax_split(
    const float* __restrict__ scores, float* __restrict__ attn,
    bf16* __restrict__ ah, bf16* __restrict__ al)
{
    const int row  = blockIdx.x * 8 + (threadIdx.x >> 5);
    const int lane = threadIdx.x & 31;
    const float* s = scores + (size_t)row * 256;

    float v[8];
    float mx = -1e30f;
#pragma unroll
    for (int j = 0; j < 8; j++) { v[j] = s[lane + 32 * j]; mx = fmaxf(mx, v[j]); }
#pragma unroll
    for (int o = 16; o; o >>= 1) mx = fmaxf(mx, __shfl_xor_sync(0xffffffffu, mx, o));
    float sum = 0.f;
#pragma unroll
    for (int j = 0; j < 8; j++) { v[j] = expf(v[j] - mx); sum += v[j]; }
#pragma unroll
    for (int o = 16; o; o >>= 1) sum += __shfl_xor_sync(0xffffffffu, sum, o);
    const float inv = 1.f / sum;

    float* a  = attn + (size_t)row * 256;
    bf16* hh = ah + (size_t)row * 256;
    bf16* ll_ = al + (size_t)row * 256;
#pragma unroll
    for (int j = 0; j < 8; j++) {
        float p = v[j] * inv;
        a[lane + 32 * j] = p;
        bf16 h, l; split2(p, h, l);
        hh[lane + 32 * j] = h; ll_[lane + 32 * j] = l;
    }
}

// ---------------------------------------------------------------------------
// residual + LayerNorm (ddof=1, eps added to sigma)
// ---------------------------------------------------------------------------
__global__ __launch_bounds__(256) void ln_kernel(
    const float* __restrict__ fc, const float* __restrict__ q,
    const float* __restrict__ ga, const float* __restrict__ gb,
    float* __restrict__ out)
{
    const int row = blockIdx.x;
    const float* f  = fc + (size_t)row * DMODEL;
    const float* qq = q  + (size_t)row * DMODEL;
    const int tid = threadIdx.x;

    float zv[4];
    float s = 0.f, ss = 0.f;
#pragma unroll
    for (int j = 0; j < 4; j++) {
        float zz = f[tid + 256 * j] + qq[tid + 256 * j];
        zv[j] = zz; s += zz; ss += zz * zz;
    }
    __shared__ float rs[8], rss[8];
#pragma unroll
    for (int o = 16; o; o >>= 1) {
        s  += __shfl_xor_sync(0xffffffffu, s, o);
        ss += __shfl_xor_sync(0xffffffffu, ss, o);
    }
    if ((tid & 31) == 0) { rs[tid >> 5] = s; rss[tid >> 5] = ss; }
    __syncthreads();
    if (tid < 32) {
        float a = (tid < 8) ? rs[tid] : 0.f;
        float b = (tid < 8) ? rss[tid] : 0.f;
#pragma unroll
        for (int o = 4; o; o >>= 1) {
            a += __shfl_xor_sync(0xffffffffu, a, o);
            b += __shfl_xor_sync(0xffffffffu, b, o);
        }
        if (tid == 0) { rs[0] = a; rss[0] = b; }
    }
    __syncthreads();
    const float mu  = rs[0] * (1.f / DMODEL);
    const float var = (rss[0] - (float)DMODEL * mu * mu) * (1.f / (DMODEL - 1));
    const float inv = 1.f / (sqrtf(fmaxf(var, 0.f)) + 1e-3f);
    float* o_ = out + (size_t)row * DMODEL;
#pragma unroll
    for (int j = 0; j < 4; j++) {
        const int col = tid + 256 * j;
        o_[col] = (zv[j] - mu) * inv * ga[col] + gb[col];
    }
}

// ---------------------------------------------------------------------------
extern "C" void kernel_launch(void* const* d_in, const int* in_sizes, int n_in,
                              void* d_out, int out_size)
{
    const float* q    = (const float*)d_in[0];
    const float* k    = (const float*)d_in[1];
    const float* v    = (const float*)d_in[2];
    const float* cq_w = (const float*)d_in[3];
    const float* cq_b = (const float*)d_in[4];
    const float* ck_w = (const float*)d_in[5];
    const float* ck_b = (const float*)d_in[6];
    const float* cv_w = (const float*)d_in[7];
    const float* cv_b = (const float*)d_in[8];
    const float* w_qs = (const float*)d_in[9];
    const float* w_ks = (const float*)d_in[10];
    const float* w_vs = (const float*)d_in[11];
    const float* pj_w = (const float*)d_in[12];
    const float* pj_b = (const float*)d_in[13];
    const float* fc_w = (const float*)d_in[14];
    const float* fc_b = (const float*)d_in[15];
    const float* ln_a = (const float*)d_in[16];
    const float* ln_b = (const float*)d_in[17];

    bf16 *bh = nullptr, *bl = nullptr; float* fs = nullptr;
    cudaGetSymbolAddress((void**)&bh, g_bh);
    cudaGetSymbolAddress((void**)&bl, g_bl);
    cudaGetSymbolAddress((void**)&fs, g_fs);

    cudaFuncSetAttribute(gemm_tc, cudaFuncAttributeMaxDynamicSharedMemorySize, GSMEM);

    float* out  = (float*)d_out;
    float* attn = out + (size_t)BATCH * DT * LLEN;

    // ---- prep ----
    zero_pads<<<1536, 256>>>(bh + O_QT, bl + O_QT);     // covers QT,KT,VT,PRT
    pack_bias<<<1, 256>>>(cq_b, ck_b, cv_b, fs + F_BIAS);
    transpose_split<<<dim3(32, 8, 32), 256>>>(q, bh + O_QT, bl + O_QT,
                                              256, 1024, 262144, 265216, 6);
    transpose_split<<<dim3(32, 8, 32), 256>>>(k, bh + O_KT, bl + O_KT,
                                              256, 1024, 262144, 265216, 6);
    transpose_split<<<dim3(32, 8, 32), 256>>>(v, bh + O_VT, bl + O_VT,
                                              256, 1024, 262144, 265216, 6);
    transpose_split<<<dim3(8, 32, 8), 256>>>(w_qs, bh + O_WQT, bl + O_WQT,
                                             1024, 256, 262144, 262144, 0);
    transpose_split<<<dim3(8, 32, 8), 256>>>(w_ks, bh + O_WKT, bl + O_WKT,
                                             1024, 256, 262144, 262144, 0);
    transpose_split<<<dim3(8, 32, 8), 256>>>(w_vs, bh + O_WVT, bl + O_WVT,
                                             1024, 256, 262144, 262144, 0);
    conv_w_prep<<<3328, 256>>>(cq_w, bh + O_WCQ, bl + O_WCQ);
    conv_w_prep<<<3328, 256>>>(ck_w, bh + O_WCK, bl + O_WCK);
    conv_w_prep<<<3328, 256>>>(cv_w, bh + O_WCV, bl + O_WCV);
    conv_w_prep<<<3328, 256>>>(fc_w, bh + O_WFC, bl + O_WFC);
    split_k<<<8192, 256>>>(pj_w, bh + O_PJW, bl + O_PJW, 2097152);

    // ---- 1. conv q/k/v MERGED: z1 = conv idx (0..2), z2 = batch ----
    gemm_tc<<<dim3(8, 2, 96), 256, GSMEM>>>(
        bh + O_WCQ, bl + O_WCQ, bh + O_QT, bl + O_QT,
        nullptr, bh + O_QB, bl + O_QB, 256, 256, 1024,
        851968, 0, 8486912, 265216, 8388608, 262144,
        65536, 256, 8, 13, 32, 1.f, fs + F_BIAS, 256);

    // ---- 2. head projections (z1 = h, z2 = b) ----
    const dim3 ghb(2, 2, 256);
    gemm_tc<<<ghb, 256, GSMEM>>>(bh + O_QB, bl + O_QB, bh + O_WQT, bl + O_WQT,
        nullptr, bh + O_QS, bl + O_QS, 1024, 1024, 256,
        0, 262144, 262144, 0, 2097152, 65536, 0, 0, 32, 1, 32, 1.f, nullptr, 0);
    gemm_tc<<<ghb, 256, GSMEM>>>(bh + O_KB, bl + O_KB, bh + O_WKT, bl + O_WKT,
        nullptr, bh + O_KS, bl + O_KS, 1024, 1024, 256,
        0, 262144, 262144, 0, 2097152, 65536, 0, 0, 32, 1, 32, 1.f, nullptr, 0);
    gemm_tc<<<ghb, 256, GSMEM>>>(bh + O_WVT, bl + O_WVT, bh + O_VB, bl + O_VB,
        nullptr, bh + O_VST, bl + O_VST, 1024, 1024, 256,
        262144, 0, 0, 262144, 2097152, 65536, 0, 0, 32, 1, 32, 1.f, nullptr, 0);

    // ---- 3. scores = qs . ks^T / 32 -> fp32 ----
    gemm_tc<<<ghb, 256, GSMEM>>>(bh + O_QS, bl + O_QS, bh + O_KS, bl + O_KS,
        fs + F_SC, nullptr, nullptr, 256, 256, 256,
        2097152, 65536, 2097152, 65536, 2097152, 65536, 0, 0, 8, 1, 32,
        1.f / 32.f, nullptr, 0);

    // ---- 4. softmax -> attns (d_out) + split arena ----
    softmax_split<<<8192, 256>>>(fs + F_SC, attn, bh + O_ATT, bl + O_ATT);

    // ---- 5. out = attn . vsT^T -> cat (B, 256, 2048) ----
    gemm_tc<<<ghb, 256, GSMEM>>>(bh + O_ATT, bl + O_ATT, bh + O_VST, bl + O_VST,
        nullptr, bh + O_CAT, bl + O_CAT, 256, 256, 2048,
        2097152, 65536, 2097152, 65536, 256, 524288, 0, 0, 8, 1, 32,
        1.f, nullptr, 0);

    // ---- 6. proj, transposed: C[dm][t] -> prT (pad row offset 6) ----
    gemm_tc<<<dim3(2, 8, 32), 256, GSMEM>>>(bh + O_PJW, bl + O_PJW,
        bh + O_CAT, bl + O_CAT,
        nullptr, bh + O_PRT + 1536, bl + O_PRT + 1536, 2048, 2048, 256,
        0, 0, 0, 524288, 0, 265216, 0, 0, 64, 1, 32, 1.f, pj_b, 0);

    // ---- 7. fc conv: M=256(o), N=1024(l), K=256 x 13 -> fp32 ----
    gemm_tc<<<dim3(8, 2, 32), 256, GSMEM>>>(
        bh + O_WFC, bl + O_WFC, bh + O_PRT, bl + O_PRT,
        fs + F_FC, nullptr, nullptr, 256, 256, 1024,
        0, 0, 0, 265216, 0, 262144, 65536, 256, 8, 13, 32, 1.f, fc_b, 0);

    // ---- 8. residual + LayerNorm ----
    ln_kernel<<<BATCH * DT, 256>>>(fs + F_FC, q, ln_a, ln_b, out);

    (void)in_sizes; (void)n_in; (void)out_size;
}